// round 10
// baseline (speedup 1.0000x reference)
#include <cuda_runtime.h>
#include <stdint.h>

// ---------------------------------------------------------------------------
// ClipperEventEncoder: LIF recurrence (tau=2, v_th=1, hard reset) ->
// conv3x3(1->4)+relu -> conv3x3(4->1)+relu -> mean over T.
//
// R10 = R9 resubmission (R9 never ran: broker-side container failure, same
// error previously seen against an empty stub and against sources that
// passed unchanged on retry).
//
// Design: ONE kernel, ZERO cross-block dependencies. Each of 256 blocks
// owns a 32x32 output tile and computes the LIF recurrence for the tile's
// 36x36 input region (2-px halo) itself -- redundant halo compute instead
// of a producer/consumer handoff (which regressed in R7/R8: tail skew +
// resource shaping stretched the streaming phase). Halo re-reads are
// deduped in L2 (neighbor blocks stream the same lines concurrently), so
// DRAM traffic stays at the 100.7 MB floor.
//
// Per thread: 3 pixel slots x 96 steps, loads register-batched 12 at a
// time (4 steps x 3 px) -> MLP-rich streaming (the pattern that took the
// split kernel from 2.4 to 7.4 TB/s in R5). Spike bits packed in registers
// (3 words/pixel). One block-wide OR decides spikiness; with x ~ U[0,1)
// the membrane potential v=(v+x)/2 stays < 1 forever (exactly in fp32:
// near threshold x-v is Sterbenz-exact and the sum is <= 1-2^-24), so
// every block takes the fast path: write 1024 zeros. The spiky fallback
// (dump bits to smem, per-step skip + shared-memory conv) is fully correct
// for arbitrary inputs.
// ---------------------------------------------------------------------------

#define IMG_H 512
#define IMG_W 512
#define HW (IMG_H * IMG_W)
#define T_STEPS 96

#define TILE 32
#define REG 36                    // region edge = TILE + 4 (2-px halo)
#define NPX (REG * REG)           // 1296 region pixels
#define NTHR 512
#define HREG 34                   // h region edge = TILE + 2

__global__ void __launch_bounds__(NTHR, 2)
snn_tile_kernel(const float* __restrict__ x,     // [96, 512, 512]
                const float* __restrict__ w1,    // [4,1,3,3]
                const float* __restrict__ w2,    // [1,4,3,3]
                float* __restrict__ out)         // [512,512]
{
    __shared__ uint32_t sany[4];
    __shared__ uint32_t sbits[NPX * 3];          // region spike bits (spiky path)
    __shared__ float    ssp[REG][REG + 4];       // decoded spikes (spiky path)
    __shared__ float    sh[4][HREG][HREG + 2];   // relu(conv1) (spiky path)
    __shared__ float    sw1[36];
    __shared__ float    sw2[36];

    const int tid = threadIdx.x;
    const int x0  = (blockIdx.x & 15) * TILE;
    const int y0  = (blockIdx.x >> 4) * TILE;

    if (tid < 4) sany[tid] = 0u;
    __syncthreads();                             // sany init visible to all

    // ---- per-slot pixel setup (3 slots: i = tid, tid+512, tid+1024) ------
    const float* p[3];
    bool valid[3];
    #pragma unroll
    for (int k = 0; k < 3; ++k) {
        const int i  = tid + k * NTHR;
        const int yy = i / REG, xx = i % REG;
        const int gy = y0 - 2 + yy, gx = x0 - 2 + xx;
        valid[k] = (i < NPX) && (gy >= 0) && (gy < IMG_H) && (gx >= 0) && (gx < IMG_W);
        // invalid slots load pixel 0 (harmless); their bits are zeroed below
        p[k] = x + (valid[k] ? (size_t)gy * IMG_W + gx : 0);
    }

    float    v[3]       = {0.0f, 0.0f, 0.0f};
    uint32_t bits[3][3] = {{0u,0u,0u},{0u,0u,0u},{0u,0u,0u}};

    // ---- LIF recurrence: 12-load register batches, fully unrolled --------
    #pragma unroll
    for (int tb = 0; tb < T_STEPS; tb += 4) {
        float r[4][3];
        #pragma unroll
        for (int j = 0; j < 4; ++j)
            #pragma unroll
            for (int k = 0; k < 3; ++k)
                r[j][k] = __ldcs(p[k] + (size_t)(tb + j) * HW);
        #pragma unroll
        for (int j = 0; j < 4; ++j) {
            const int c = (tb + j) >> 5, sb = (tb + j) & 31;
            #pragma unroll
            for (int k = 0; k < 3; ++k) {
                v[k] = v[k] + (r[j][k] - v[k]) * 0.5f;       // v + (x-v)/tau
                const uint32_t s = (v[k] >= 1.0f) ? 1u : 0u;
                bits[k][c] |= s << sb;
                if (s) v[k] = 0.0f;                          // hard reset
            }
        }
    }

    // Invalid slots (outside image / i >= NPX) must not spike.
    #pragma unroll
    for (int k = 0; k < 3; ++k)
        if (!valid[k]) { bits[k][0] = 0u; bits[k][1] = 0u; bits[k][2] = 0u; }

    // ---- block-wide "any spike at step t" masks --------------------------
    uint32_t c0 = bits[0][0] | bits[1][0] | bits[2][0];
    uint32_t c1 = bits[0][1] | bits[1][1] | bits[2][1];
    uint32_t c2 = bits[0][2] | bits[1][2] | bits[2][2];
    c0 = __reduce_or_sync(0xffffffffu, c0);
    c1 = __reduce_or_sync(0xffffffffu, c1);
    c2 = __reduce_or_sync(0xffffffffu, c2);
    if ((tid & 31) == 0) {
        if (c0) atomicOr(&sany[0], c0);
        if (c1) atomicOr(&sany[1], c1);
        if (c2) atomicOr(&sany[2], c2);
    }
    __syncthreads();

    const uint32_t a0 = sany[0], a1 = sany[1], a2 = sany[2];

    float acc[2] = {0.0f, 0.0f};

    if (a0 | a1 | a2) {
        // ---- rare path: publish region bits to smem, load weights --------
        #pragma unroll
        for (int k = 0; k < 3; ++k) {
            const int i = tid + k * NTHR;
            if (i < NPX) {
                sbits[i * 3 + 0] = bits[k][0];
                sbits[i * 3 + 1] = bits[k][1];
                sbits[i * 3 + 2] = bits[k][2];
            }
        }
        if (tid < 36) { sw1[tid] = w1[tid]; sw2[tid] = w2[tid]; }
        __syncthreads();

        for (int t = 0; t < T_STEPS; ++t) {
            const uint32_t chunk = (t < 32) ? a0 : (t < 64) ? a1 : a2;
            if (!((chunk >> (t & 31)) & 1u)) continue;       // uniform branch

            // ---- decode region spike bits -> float tile -------------------
            for (int i = tid; i < NPX; i += NTHR) {
                const uint32_t w = sbits[i * 3 + (t >> 5)];
                ssp[i / REG][i % REG] = ((w >> (t & 31)) & 1u) ? 1.0f : 0.0f;
            }
            __syncthreads();

            // ---- conv1 (1->4) + relu over the 34x34 h region --------------
            for (int i = tid; i < HREG * HREG; i += NTHR) {
                const int hy = i / HREG, hx = i % HREG;
                float b0 = 0.f, b1 = 0.f, b2 = 0.f, b3 = 0.f;
                #pragma unroll
                for (int ky = 0; ky < 3; ++ky) {
                    #pragma unroll
                    for (int kx = 0; kx < 3; ++kx) {
                        const float s = ssp[hy + ky][hx + kx];
                        const int  k = ky * 3 + kx;
                        b0 += sw1[ 0 + k] * s;
                        b1 += sw1[ 9 + k] * s;
                        b2 += sw1[18 + k] * s;
                        b3 += sw1[27 + k] * s;
                    }
                }
                sh[0][hy][hx] = fmaxf(b0, 0.f);
                sh[1][hy][hx] = fmaxf(b1, 0.f);
                sh[2][hy][hx] = fmaxf(b2, 0.f);
                sh[3][hy][hx] = fmaxf(b3, 0.f);
            }
            __syncthreads();

            // ---- conv2 (4->1) + relu, accumulate (2 outputs/thread) -------
            #pragma unroll
            for (int k = 0; k < 2; ++k) {
                const int o  = tid + NTHR * k;
                const int oy = o >> 5;
                const int ox = o & 31;
                float a = 0.0f;
                #pragma unroll
                for (int c = 0; c < 4; ++c) {
                    #pragma unroll
                    for (int ky = 0; ky < 3; ++ky) {
                        #pragma unroll
                        for (int kx = 0; kx < 3; ++kx) {
                            a += sw2[c * 9 + ky * 3 + kx] * sh[c][oy + ky][ox + kx];
                        }
                    }
                }
                acc[k] += fmaxf(a, 0.0f);
            }
            __syncthreads();   // sh/ssp reuse next iteration
        }
    }

    // ---- mean over T and store -------------------------------------------
    const float inv_t = 1.0f / (float)T_STEPS;
    #pragma unroll
    for (int k = 0; k < 2; ++k) {
        const int o  = tid + NTHR * k;
        const int oy = o >> 5;
        const int ox = o & 31;
        out[(size_t)(y0 + oy) * IMG_W + (x0 + ox)] = acc[k] * inv_t;
    }
}

// ---------------------------------------------------------------------------
extern "C" void kernel_launch(void* const* d_in, const int* in_sizes, int n_in,
                              void* d_out, int out_size)
{
    const float* x_seq = (const float*)d_in[0];   // [96, 512, 512] fp32
    const float* w1    = (const float*)d_in[1];   // [4,1,3,3] fp32
    const float* w2    = (const float*)d_in[2];   // [1,4,3,3] fp32
    float*       out   = (float*)d_out;           // [512,512] fp32

    snn_tile_kernel<<<256, NTHR>>>(x_seq, w1, w2, out);   // one block per tile
}

// round 12
// speedup vs baseline: 1.4509x; 1.4509x over previous
#include <cuda_runtime.h>
#include <stdint.h>

// ---------------------------------------------------------------------------
// ClipperEventEncoder: LIF recurrence (tau=2, v_th=1, hard reset) ->
// conv3x3(1->4)+relu -> conv3x3(4->1)+relu -> mean over T.
//
// R12 = R11 resubmission (R11 never ran: broker-side container failure,
// the 5th such; two prior failures passed byte-identical on retry).
//
// Design: measured-best two-kernel split (R5: lif 14.9us @ 7.4TB/s + conv
// 5.6us) with both overheads removed. All three fusion variants (R7/R8/
// R10) measured ~27us -- aligned 1-D streaming beats every fused layout.
//  k1 (lif): R5's proven 2px/thread, 16-load register-batch stream.
//   (a) NO mask zero-fill -- __device__ globals are zero at module load
//   and non-spiking words are never written, so readers see zeros; spiking
//   words rewrite all 96 entries each run. Saves 3.1 MB of writes.
//   (b) each block writes its 256 output pixels as ZEROS (+1 MB, ~0.13us).
//   (c) spiking warps bump g_any_spike (zero-spike input: no atomic ever).
//  k2 (conv): read g_any_spike once; 0 -> return (near-null kernel). Else
//   full Phase-A + per-step-skip shared-memory conv, overwriting k1's
//   zeros. Correct for arbitrary inputs; for this input (x ~ U[0,1) keeps
//   v=(v+x)/2 < 1 forever -- exact in fp32: near threshold x-v is
//   Sterbenz-exact and the sum <= 1-2^-24 never rounds to 1.0) k2 is a
//   ~1us no-op.
// ---------------------------------------------------------------------------

#define IMG_H 512
#define IMG_W 512
#define HW (IMG_H * IMG_W)
#define T_STEPS 96
#define WPR (IMG_W / 32)                 // 16 mask words per image row
#define NWORDS (IMG_H * WPR)             // 8192 words per time step

// Mask layout: [word][t]. Only written for words that spike (all 96 t);
// everything else stays module-load zero, which is what readers need.
__device__ uint32_t g_spike_mask[NWORDS * T_STEPS];   // 3.1 MB
// Per-word timestep summary (any_t0..31, any_t32..63, any_t64..95, 0);
// written unconditionally by every warp each run.
__device__ uint4 g_word_any4[NWORDS];                 // 128 KB
// Global spike indicator: bumped once per spiking warp, never reset.
// Zero-spike input: stays 0 forever. Nonzero only ever routes k2 to the
// full conv path, whose output depends solely on masks/summaries.
__device__ unsigned int g_any_spike;

#define TILE 32
#define SREG 36          // spike region edge (TILE + 4)
#define HREG 34          // h region edge     (TILE + 2)

// ---------------------------------------------------------------------------
// Kernel 1: LIF recurrence. 2 pixels/thread (pxA = seg+lane, pxB = +32) so
// each warp owns mask words 2*gw, 2*gw+1 with lane<->bit identity.
// 1024 blocks x 128 threads. Also writes this block's 256 output pixels
// as zeros (k2 overwrites them only when spikes exist).
// ---------------------------------------------------------------------------
__global__ void __launch_bounds__(128)
lif_spike_kernel(const float* __restrict__ x, float* __restrict__ out)
{
    const int tid   = threadIdx.x;
    const int lane  = tid & 31;
    const int gw    = blockIdx.x * 4 + (tid >> 5);       // global warp id
    const int seg   = gw * 64;
    const int pxA   = seg + lane;
    const int pxB   = pxA + 32;
    const int wordA = gw * 2;
    const int wordB = wordA + 1;

    float vA = 0.0f, vB = 0.0f;
    uint32_t bitsA[3], bitsB[3];

    // Fully unrolled: compile-time shifts; ptxas front-batches each 16-load
    // group -> MLP ~ 16, DRAM-bound (measured 7.4 TB/s in R5).
    #pragma unroll
    for (int c = 0; c < 3; ++c) {
        uint32_t aA = 0u, aB = 0u;
        #pragma unroll
        for (int tb = 0; tb < 32; tb += 8) {
            const float* __restrict__ base = x + (size_t)(c * 32 + tb) * HW;
            float ra[8], rb[8];
            #pragma unroll
            for (int j = 0; j < 8; ++j) {
                ra[j] = __ldcs(base + (size_t)j * HW + pxA);
                rb[j] = __ldcs(base + (size_t)j * HW + pxB);
            }
            #pragma unroll
            for (int j = 0; j < 8; ++j) {
                vA = vA + (ra[j] - vA) * 0.5f;               // v + (x-v)/tau
                const uint32_t sA = (vA >= 1.0f) ? 1u : 0u;
                aA |= sA << (tb + j);
                if (sA) vA = 0.0f;                           // hard reset

                vB = vB + (rb[j] - vB) * 0.5f;
                const uint32_t sB = (vB >= 1.0f) ? 1u : 0u;
                aB |= sB << (tb + j);
                if (sB) vB = 0.0f;
            }
        }
        bitsA[c] = aA;
        bitsB[c] = aB;
    }

    uint32_t anyA[3], anyB[3];
    #pragma unroll
    for (int c = 0; c < 3; ++c) {
        anyA[c] = __reduce_or_sync(0xffffffffu, bitsA[c]);
        anyB[c] = __reduce_or_sync(0xffffffffu, bitsB[c]);
    }
    if (lane == 0) {
        g_word_any4[wordA] = make_uint4(anyA[0], anyA[1], anyA[2], 0u);
        g_word_any4[wordB] = make_uint4(anyB[0], anyB[1], anyB[2], 0u);
    }

    const uint32_t spA = anyA[0] | anyA[1] | anyA[2];        // warp-uniform
    const uint32_t spB = anyB[0] | anyB[1] | anyB[2];

    // Rare path only: write the word's full 96-entry mask column and flag.
    if (spA != 0u) {
        uint32_t* wA = &g_spike_mask[(size_t)wordA * T_STEPS];
        #pragma unroll 1
        for (int t = 0; t < T_STEPS; ++t) {
            const int c = t >> 5, s = t & 31;
            const uint32_t m = __ballot_sync(0xffffffffu, (bitsA[c] >> s) & 1u);
            if (lane == 0) wA[t] = m;
        }
    }
    if (spB != 0u) {
        uint32_t* wB = &g_spike_mask[(size_t)wordB * T_STEPS];
        #pragma unroll 1
        for (int t = 0; t < T_STEPS; ++t) {
            const int c = t >> 5, s = t & 31;
            const uint32_t m = __ballot_sync(0xffffffffu, (bitsB[c] >> s) & 1u);
            if (lane == 0) wB[t] = m;
        }
    }
    if ((spA | spB) != 0u && lane == 0) atomicAdd(&g_any_spike, 1u);

    // Speculative output zeros: this block's 256 contiguous output pixels.
    // (k2 overwrites every tile it actually computes.)
    float2* oz = reinterpret_cast<float2*>(out + (size_t)blockIdx.x * 256);
    __stcs(&oz[tid], make_float2(0.0f, 0.0f));
}

// ---------------------------------------------------------------------------
// Kernel 2: near-null in the common case. If any spike exists anywhere,
// run the per-tile Phase A + per-step-skip shared-memory conv (overwrites
// k1's speculative zeros).
// ---------------------------------------------------------------------------
__global__ void __launch_bounds__(256, 4)
conv_accum_kernel(const float* __restrict__ w1,   // [4,1,3,3]
                  const float* __restrict__ w2,   // [1,4,3,3]
                  float* __restrict__ out)        // [512,512]
{
    __shared__ uint32_t sgate;
    __shared__ uint32_t sany[4];
    __shared__ float    ssp[SREG][SREG + 4];
    __shared__ float    sh[4][HREG][HREG + 2];
    __shared__ float    sw1[36];
    __shared__ float    sw2[36];

    const int tid = threadIdx.x;

    if (tid == 0) sgate = *(volatile unsigned int*)&g_any_spike;
    __syncthreads();
    if (sgate == 0u) return;                     // common case: k1's zeros stand

    const int x0  = blockIdx.x * TILE;
    const int y0  = blockIdx.y * TILE;
    const int wx0 = x0 >> 5;

    if (tid < 36) { sw1[tid] = w1[tid]; sw2[tid] = w2[tid]; }
    if (tid < 4)  sany[tid] = 0u;
    __syncthreads();

    // ---- Phase A: OR halo per-word summaries (one LDG.128 each) ----------
    // Words covering columns [x0-32, x0+63] x rows [y0-2, y0+33]: superset
    // of the true 2-px halo (never skips a needed step).
    {
        uint32_t l0 = 0u, l1 = 0u, l2 = 0u;
        for (int i = tid; i < 36 * 3; i += 256) {
            const int r   = i / 3;
            const int wxo = i % 3 - 1;
            const int gy  = y0 - 2 + r;
            const int wx  = wx0 + wxo;
            if (gy >= 0 && gy < IMG_H && wx >= 0 && wx < WPR) {
                const uint4 a = __ldcg(&g_word_any4[gy * WPR + wx]);
                l0 |= a.x; l1 |= a.y; l2 |= a.z;
            }
        }
        if (l0) atomicOr(&sany[0], l0);
        if (l1) atomicOr(&sany[1], l1);
        if (l2) atomicOr(&sany[2], l2);
    }
    __syncthreads();

    const uint32_t a0 = sany[0], a1 = sany[1], a2 = sany[2];

    float acc[4] = {0.0f, 0.0f, 0.0f, 0.0f};

    if (a0 | a1 | a2) {
        for (int t = 0; t < T_STEPS; ++t) {
            const uint32_t chunk = (t < 32) ? a0 : (t < 64) ? a1 : a2;
            if (!((chunk >> (t & 31)) & 1u)) continue;       // uniform branch

            // ---- decode spike bits -> float tile (zero-padded at edges) ---
            for (int i = tid; i < SREG * SREG; i += 256) {
                const int yy = i / SREG, xx = i % SREG;
                const int gy = y0 - 2 + yy, gx = x0 - 2 + xx;
                float s = 0.0f;
                if (gy >= 0 && gy < IMG_H && gx >= 0 && gx < IMG_W) {
                    const int w = gy * WPR + (gx >> 5);
                    const uint32_t m = __ldcg(&g_spike_mask[(size_t)w * T_STEPS + t]);
                    s = ((m >> (gx & 31)) & 1u) ? 1.0f : 0.0f;
                }
                ssp[yy][xx] = s;
            }
            __syncthreads();

            // ---- conv1 (1->4) + relu over the 34x34 h region --------------
            for (int i = tid; i < HREG * HREG; i += 256) {
                const int hy = i / HREG, hx = i % HREG;
                float b0 = 0.f, b1 = 0.f, b2 = 0.f, b3 = 0.f;
                #pragma unroll
                for (int ky = 0; ky < 3; ++ky) {
                    #pragma unroll
                    for (int kx = 0; kx < 3; ++kx) {
                        const float s = ssp[hy + ky][hx + kx];
                        const int  k = ky * 3 + kx;
                        b0 += sw1[ 0 + k] * s;
                        b1 += sw1[ 9 + k] * s;
                        b2 += sw1[18 + k] * s;
                        b3 += sw1[27 + k] * s;
                    }
                }
                sh[0][hy][hx] = fmaxf(b0, 0.f);
                sh[1][hy][hx] = fmaxf(b1, 0.f);
                sh[2][hy][hx] = fmaxf(b2, 0.f);
                sh[3][hy][hx] = fmaxf(b3, 0.f);
            }
            __syncthreads();

            // ---- conv2 (4->1) + relu, accumulate (4 outputs/thread) -------
            #pragma unroll
            for (int k = 0; k < 4; ++k) {
                const int o  = tid + 256 * k;
                const int oy = o >> 5;
                const int ox = o & 31;
                float a = 0.0f;
                #pragma unroll
                for (int c = 0; c < 4; ++c) {
                    #pragma unroll
                    for (int ky = 0; ky < 3; ++ky) {
                        #pragma unroll
                        for (int kx = 0; kx < 3; ++kx) {
                            a += sw2[c * 9 + ky * 3 + kx] * sh[c][oy + ky][ox + kx];
                        }
                    }
                }
                acc[k] += fmaxf(a, 0.0f);
            }
            __syncthreads();   // sh/ssp reuse next iteration
        }
    }

    // ---- mean over T and store (overwrites k1's speculative zeros) -------
    const float inv_t = 1.0f / (float)T_STEPS;
    #pragma unroll
    for (int k = 0; k < 4; ++k) {
        const int o  = tid + 256 * k;
        const int oy = o >> 5;
        const int ox = o & 31;
        out[(size_t)(y0 + oy) * IMG_W + (x0 + ox)] = acc[k] * inv_t;
    }
}

// ---------------------------------------------------------------------------
extern "C" void kernel_launch(void* const* d_in, const int* in_sizes, int n_in,
                              void* d_out, int out_size)
{
    const float* x_seq = (const float*)d_in[0];   // [96, 512, 512] fp32
    const float* w1    = (const float*)d_in[1];   // [4,1,3,3] fp32
    const float* w2    = (const float*)d_in[2];   // [1,4,3,3] fp32
    float*       out   = (float*)d_out;           // [512,512] fp32

    lif_spike_kernel<<<HW / 256, 128>>>(x_seq, out);
    conv_accum_kernel<<<dim3(IMG_W / TILE, IMG_H / TILE), 256>>>(w1, w2, out);
}